// round 13
// baseline (speedup 1.0000x reference)
#include <cuda_runtime.h>
#include <cuda_bf16.h>
#include <stdint.h>

#define B_TOT 32768
#define N_DIM 512
#define SOLVE_ITERS 10
#define NTOT 290                  // 29 slices/pair * 10 pairs; <=296 resident @2 CTA/SM
#define NPAIRS 10
#define NEARLY 100                // early consumers: 10 slices/pair over stages [0,512)
#define NLATE 190                 // late consumers: 19 slices/pair over stages [512,1024)
#define SOLVE_BASE 100            // solver CTAs: cb in [100,132)
#define NSOLVE 32
#define NPH1 258                  // phase-1 producers (non-solvers)
#define NPH2 190                  // phase-2 producers (late non-solvers + solvers)
#define HALF_ROWS 16384
#define W2SUM 538                 // ph2 weights: 32 solvers*2 + 158 others*3

// ------------- device scratch (no allocations; zero at load) -------------
__device__ __nv_bfloat16 g_R[(size_t)B_TOT * N_DIM];  // 32 MB bf16 r
__device__ float g_v[N_DIM];
__device__ float g_p[2][N_DIM];
__device__ float g_colsum[N_DIM];
__device__ double g_second;
__device__ unsigned g_bar_count, g_bar_gen;      // 32-CTA solve barrier
__device__ unsigned g_cntA, g_cntB;              // half-barrier arrive counters
__device__ unsigned g_done, g_vcnt, g_v_ready;

__constant__ int c_pi[NPAIRS] = {0,0,0,0,1,1,1,2,2,3};
__constant__ int c_pj[NPAIRS] = {0,1,2,3,1,2,3,2,3,3};

// ---- volatile acquire load: spin-safe (compiler cannot hoist/delete) ----
__device__ __forceinline__ unsigned ldv_acq(const unsigned* p) {
    unsigned v;
    asm volatile("ld.global.acquire.gpu.u32 %0, [%1];" : "=r"(v) : "l"(p) : "memory");
    return v;
}
// arrive: every thread fences its writes, then tid0 bumps the counter
__device__ __forceinline__ void arrive_cnt(unsigned* cnt) {
    __threadfence();
    __syncthreads();
    if (threadIdx.x == 0) atomicAdd(cnt, 1u);
}
__device__ __forceinline__ void wait_cnt(const unsigned* cnt, unsigned target) {
    if (threadIdx.x == 0) {
        while (ldv_acq(cnt) < target) __nanosleep(30);
        __threadfence();
    }
    __syncthreads();
}

// ---- grid barrier among the 32 solve CTAs ----
__device__ __forceinline__ void solve_barrier(unsigned target) {
    __syncthreads();
    if (threadIdx.x == 0) {
        __threadfence();
        if (atomicAdd(&g_bar_count, 1u) == NSOLVE - 1) {
            atomicExch(&g_bar_count, 0u);
            __threadfence();
            atomicExch(&g_bar_gen, target);
        } else {
            while (ldv_acq(&g_bar_gen) < target) __nanosleep(20);
        }
        __threadfence();
    }
    __syncthreads();
}

// -------------------------- GEMM helpers --------------------------
__device__ __forceinline__ void cp16(void* smem, const void* gmem) {
    unsigned saddr = (unsigned)__cvta_generic_to_shared(smem);
    asm volatile("cp.async.cg.shared.global [%0], [%1], 16;\n" :: "r"(saddr), "l"(gmem));
}
__device__ __forceinline__ void ldsm4t(unsigned& d0, unsigned& d1, unsigned& d2, unsigned& d3,
                                       const __nv_bfloat16* p) {
    unsigned a = (unsigned)__cvta_generic_to_shared(p);
    asm volatile("ldmatrix.sync.aligned.m8n8.x4.trans.shared.b16 {%0,%1,%2,%3}, [%4];\n"
                 : "=r"(d0), "=r"(d1), "=r"(d2), "=r"(d3) : "r"(a));
}
__device__ __forceinline__ void mma16816(float* c, const unsigned* a, const unsigned* b) {
    asm volatile(
        "mma.sync.aligned.m16n8k16.row.col.f32.bf16.bf16.f32 "
        "{%0,%1,%2,%3}, {%4,%5,%6,%7}, {%8,%9}, {%0,%1,%2,%3};\n"
        : "+f"(c[0]), "+f"(c[1]), "+f"(c[2]), "+f"(c[3])
        : "r"(a[0]), "r"(a[1]), "r"(a[2]), "r"(a[3]), "r"(b[0]), "r"(b[1]));
}

// ==================== one persistent kernel, pipelined halves ====================
__global__ void __launch_bounds__(256, 2) mono_k(const float* __restrict__ Gamma,
                                                 const float* __restrict__ SR,
                                                 const float* __restrict__ lsh,
                                                 const float* __restrict__ sig,
                                                 const int* __restrict__ kp,
                                                 float* __restrict__ out) {
    __shared__ __align__(16) __nv_bfloat16 smA[4][32][136];
    __shared__ __align__(16) __nv_bfloat16 smB[4][32][136];
    __shared__ float p_s[N_DIM];
    __shared__ double wsum[8];
    __shared__ bool is_last;

    const int tid  = threadIdx.x;
    const int lane = tid & 31, wid = tid >> 5;
    const int cb   = (int)blockIdx.x;
    const bool solver = (cb >= SOLVE_BASE) && (cb < SOLVE_BASE + NSOLVE);
    const bool early  = (cb < NEARLY);

    // ---------- pass1 production helper: r = exp(sig-lsh) -> bf16 g_R + colsums ----------
    auto produce = [&](int rbeg, int rend) {
        const int nchunk = (rend - rbeg) * 128;   // float4 chunks
        const int tc = tid & 127;                 // fixed column group
        float cs0 = 0.f, cs1 = 0.f, cs2 = 0.f, cs3 = 0.f;
#pragma unroll 4
        for (int idx = tid; idx < nchunk; idx += 256) {
            int r = rbeg + (idx >> 7);
            size_t off = (size_t)r * N_DIM + tc * 4;
            float4 a = __ldcs((const float4*)(lsh + off));
            float4 b = __ldcs((const float4*)(sig + off));
            float r0 = __expf(b.x - a.x), r1 = __expf(b.y - a.y);
            float r2 = __expf(b.z - a.z), r3 = __expf(b.w - a.w);
            cs0 += r0; cs1 += r1; cs2 += r2; cs3 += r3;
            __nv_bfloat162 h0 = __floats2bfloat162_rn(r0, r1);
            __nv_bfloat162 h1 = __floats2bfloat162_rn(r2, r3);
            uint2 u;
            u.x = *reinterpret_cast<unsigned*>(&h0);
            u.y = *reinterpret_cast<unsigned*>(&h1);
            *reinterpret_cast<uint2*>(&g_R[off]) = u;
        }
        atomicAdd(&g_colsum[tc * 4 + 0], cs0);
        atomicAdd(&g_colsum[tc * 4 + 1], cs1);
        atomicAdd(&g_colsum[tc * 4 + 2], cs2);
        atomicAdd(&g_colsum[tc * 4 + 3], cs3);
    };

    if (solver) {
        // ---------------- solve: v = Gamma^{-1} SR, Chebyshev, spec [1,5.5] ----------------
        const float lmin = 1.0f, lmax = 5.5f;
        const float theta = 0.5f * (lmax + lmin);
        const float delta = 0.5f * (lmax - lmin);
        const float sigma1 = theta / delta;
        float rho = 1.f / sigma1;
        const int row0 = (cb - SOLVE_BASE) * 16 + wid * 2;   // 2 rows per warp

        float4 gc[2][4];                          // register-cached Gamma rows
#pragma unroll
        for (int q = 0; q < 2; q++) {
            const float4* gr = (const float4*)(Gamma + (size_t)(row0 + q) * N_DIM);
#pragma unroll
            for (int tv = 0; tv < 4; tv++) gc[q][tv] = gr[lane + tv * 32];
        }
        float xv[2], rv[2], dv[2];
#pragma unroll
        for (int q = 0; q < 2; q++) {
            float b = SR[row0 + q];
            rv[q] = b; xv[q] = 0.f; dv[q] = b / theta;
            if (lane == 0) __stcg(&g_p[0][row0 + q], dv[q]);
        }
        unsigned gen = 0;
        for (int it = 0; it < SOLVE_ITERS; it++) {
            solve_barrier(++gen);
            int cur = it & 1;
            for (int j = tid; j < N_DIM; j += 256) p_s[j] = __ldcg(&g_p[cur][j]);
            __syncthreads();
#pragma unroll
            for (int q = 0; q < 2; q++) {
                const float4* pr = (const float4*)p_s;
                float acc = 0.f;
#pragma unroll
                for (int tv = 0; tv < 4; tv++) {
                    float4 g  = gc[q][tv];
                    float4 p4 = pr[lane + tv * 32];
                    acc += g.x * p4.x + g.y * p4.y + g.z * p4.z + g.w * p4.w;
                }
#pragma unroll
                for (int o = 16; o > 0; o >>= 1) acc += __shfl_xor_sync(0xffffffffu, acc, o);
                xv[q] += dv[q];
                rv[q] -= acc;
            }
            float rho_n = 1.f / (2.f * sigma1 - rho);
#pragma unroll
            for (int q = 0; q < 2; q++) {
                dv[q] = rho_n * rho * dv[q] + (2.f * rho_n / delta) * rv[q];
                if (lane == 0 && it + 1 < SOLVE_ITERS) __stcg(&g_p[cur ^ 1][row0 + q], dv[q]);
            }
            rho = rho_n;
            __syncthreads();
        }
        if (lane == 0) {
            __stcg(&g_v[row0], xv[0]);
            __stcg(&g_v[row0 + 1], xv[1]);
        }
        __threadfence();
        __syncthreads();
        if (tid == 0) {
            if (atomicAdd(&g_vcnt, 1u) == NSOLVE - 1) {
                __threadfence();
                atomicExch(&g_v_ready, 1u);
            }
        }
        // solvers produce a (weighted-small) phase-2 share, then sync B
        int w0 = (cb - SOLVE_BASE) * 2, w1 = w0 + 2;
        produce(HALF_ROWS + (int)(((long long)w0 * HALF_ROWS) / W2SUM),
                HALF_ROWS + (int)(((long long)w1 * HALF_ROWS) / W2SUM));
        arrive_cnt(&g_cntB);
        wait_cnt(&g_cntB, NPH2);
    } else if (early) {
        // early: phase-1 share, then wait for all of half 1
        int i = cb;                                // 0..99
        produce((int)(((long long)i * HALF_ROWS) / NPH1),
                (int)(((long long)(i + 1) * HALF_ROWS) / NPH1));
        arrive_cnt(&g_cntA);
        wait_cnt(&g_cntA, NPH1);
    } else {
        // late non-solver: ph1 share, arrive A (no wait), ph2 share, sync B
        int i = cb - NSOLVE;                       // 100..257
        produce((int)(((long long)i * HALF_ROWS) / NPH1),
                (int)(((long long)(i + 1) * HALF_ROWS) / NPH1));
        arrive_cnt(&g_cntA);
        int w0 = 64 + (cb - (SOLVE_BASE + NSOLVE)) * 3, w1 = w0 + 3;
        produce(HALF_ROWS + (int)(((long long)w0 * HALF_ROWS) / W2SUM),
                HALF_ROWS + (int)(((long long)w1 * HALF_ROWS) / W2SUM));
        arrive_cnt(&g_cntB);
        wait_cnt(&g_cntB, NPH2);
    }

    // ---------------- gemm slice: early in [0,512), late in [512,1024) ----------------
    int pair, sbeg, send;
    if (early) {
        pair = cb % NPAIRS;
        int e = cb / NPAIRS;                       // 0..9, ~51 stages each
        sbeg = (e * 512) / 10;
        send = ((e + 1) * 512) / 10;
    } else {
        int b = cb - NEARLY;
        pair = b % NPAIRS;
        int l = b / NPAIRS;                        // 0..18, ~27 stages each
        sbeg = 512 + (l * 512) / 19;
        send = 512 + ((l + 1) * 512) / 19;
    }
    const int ti = c_pi[pair] * 128, tj = c_pj[pair] * 128;
    const bool diag = (ti == tj);
    const int ns = send - sbeg;
    const int wi = wid >> 2, wj = wid & 3;         // warp tile 64(i) x 32(j)

    float acc[4][4][4];
#pragma unroll
    for (int a = 0; a < 4; a++)
#pragma unroll
        for (int b2 = 0; b2 < 4; b2++)
#pragma unroll
            for (int e = 0; e < 4; e++) acc[a][b2][e] = 0.f;

    auto load_stage = [&](int s, int buf) {
        int kbase = s * 32;
#pragma unroll
        for (int qq = 0; qq < 2; qq++) {
            int idx = tid + qq * 256;
            int row = idx >> 4, ch = idx & 15;
            const __nv_bfloat16* gbase = g_R + (size_t)(kbase + row) * N_DIM + ch * 8;
            cp16(&smA[buf][row][ch * 8], gbase + ti);
            if (!diag) cp16(&smB[buf][row][ch * 8], gbase + tj);
        }
    };

    load_stage(sbeg + 0, 0); asm volatile("cp.async.commit_group;\n");
    load_stage(sbeg + 1, 1); asm volatile("cp.async.commit_group;\n");
    load_stage(sbeg + 2, 2); asm volatile("cp.async.commit_group;\n");

    const __nv_bfloat16 (*smBsel)[32][136] = diag ? smA : smB;
    const int g = lane >> 3, r = lane & 7;
    for (int s = 0; s < ns; s++) {
        asm volatile("cp.async.wait_group 2;\n");   // stage s resident
        __syncthreads();                            // buf (s+3)&3 free for rewrite
        if (s + 3 < ns) load_stage(sbeg + s + 3, (s + 3) & 3);
        asm volatile("cp.async.commit_group;\n");
        const int buf = s & 3;
#pragma unroll
        for (int ks = 0; ks < 2; ks++) {
            int kk = ks * 16;
            unsigned afr[4][4], bfr[4][2];
#pragma unroll
            for (int mt = 0; mt < 4; mt++) {
                int i0 = wi * 64 + mt * 16;
                const __nv_bfloat16* p = &smA[buf][kk + ((g >> 1) << 3) + r][i0 + ((g & 1) << 3)];
                ldsm4t(afr[mt][0], afr[mt][1], afr[mt][2], afr[mt][3], p);
            }
#pragma unroll
            for (int n2 = 0; n2 < 2; n2++) {
                int j0 = wj * 32 + n2 * 16;
                const __nv_bfloat16* p = &smBsel[buf][kk + ((g & 1) << 3) + r][j0 + ((g >> 1) << 3)];
                unsigned d0, d1, d2, d3;
                ldsm4t(d0, d1, d2, d3, p);
                bfr[n2 * 2][0] = d0; bfr[n2 * 2][1] = d1;
                bfr[n2 * 2 + 1][0] = d2; bfr[n2 * 2 + 1][1] = d3;
            }
#pragma unroll
            for (int mt = 0; mt < 4; mt++)
#pragma unroll
                for (int nt = 0; nt < 4; nt++) mma16816(acc[mt][nt], afr[mt], bfr[nt]);
        }
    }

    // ---- v (ready long before any CTA reaches here; proven spin) ----
    if (tid == 0) { while (ldv_acq(&g_v_ready) == 0u) __nanosleep(20); }
    __syncthreads();
    for (int j = tid; j < N_DIM; j += 256) p_s[j] = __ldcg(&g_v[j]);
    __syncthreads();

    // epilogue: partial = sum Gamma_ij v_i v_j C_ij over this CTA's tile
    float partf = 0.f;
#pragma unroll
    for (int mt = 0; mt < 4; mt++) {
        int ibase = ti + wi * 64 + mt * 16 + (lane >> 2);
#pragma unroll
        for (int nt = 0; nt < 4; nt++) {
            int jbase = tj + wj * 32 + nt * 8 + 2 * (lane & 3);
#pragma unroll
            for (int e = 0; e < 4; e++) {
                int i = ibase + ((e >> 1) << 3);
                int j = jbase + (e & 1);
                partf += acc[mt][nt][e] * Gamma[(size_t)i * N_DIM + j] * p_s[i] * p_s[j];
            }
        }
    }
#pragma unroll
    for (int o = 16; o > 0; o >>= 1) partf += __shfl_xor_sync(0xffffffffu, partf, o);
    if (lane == 0) wsum[wid] = (double)partf;
    __syncthreads();
    if (tid == 0) {
        double sv = 0.0;
        for (int x = 0; x < 8; x++) sv += wsum[x];
        if (ti != tj) sv *= 2.0;   // off-diagonal tiles counted twice (symmetry)
        atomicAdd(&g_second, sv);
        __threadfence();
        unsigned d = atomicAdd(&g_done, 1u);
        is_last = (d == NTOT - 1);
    }
    __syncthreads();

    // ---------------- last CTA finalizes + resets for next replay ----------------
    if (is_last) {
        double term = 0.0;
        for (int j = tid; j < N_DIM; j += 256)
            term += (double)__ldcg(&g_colsum[j]) * (double)p_s[j] * (double)SR[j];
#pragma unroll
        for (int o = 16; o > 0; o >>= 1) term += __shfl_xor_sync(0xffffffffu, term, o);
        if (lane == 0) wsum[wid] = term;
        __syncthreads();
        if (tid == 0) {
            double sf = 0.0;
            for (int x = 0; x < 8; x++) sf += wsum[x];
            double sec = atomicAdd(&g_second, 0.0);
            double k = (double)kp[0];
            out[0] = (float)((0.5 * sec - sf) / ((double)B_TOT * k));
        }
        __syncthreads();
        for (int j = tid; j < N_DIM; j += 256) g_colsum[j] = 0.f;
        if (tid == 0) {
            g_second = 0.0;
            g_done = 0u; g_vcnt = 0u; g_v_ready = 0u;
            g_bar_count = 0u; g_bar_gen = 0u;
            g_cntA = 0u; g_cntB = 0u;
        }
    }
}

// ------------------------------ launch ------------------------------
extern "C" void kernel_launch(void* const* d_in, const int* in_sizes, int n_in,
                              void* d_out, int out_size) {
    const float* lsh = (const float*)d_in[0];
    const float* sig = (const float*)d_in[1];
    const float* SR  = (const float*)d_in[2];
    const float* Gam = (const float*)d_in[3];
    const int*   kp  = (const int*)d_in[4];

    mono_k<<<NTOT, 256>>>(Gam, SR, lsh, sig, kp, (float*)d_out);
}

// round 14
// speedup vs baseline: 1.0068x; 1.0068x over previous
#include <cuda_runtime.h>
#include <cuda_bf16.h>
#include <stdint.h>

#define B_TOT 32768
#define N_DIM 512
#define SOLVE_ITERS 10
#define NTOT 290                  // 29 slices/pair * 10 pairs; <=296 resident @2 CTA/SM
#define NPAIRS 10
#define NEARLY 100                // early consumers: 10 slices/pair over stages [0,512)
#define NLATE 190                 // late consumers: 19 slices/pair over stages [512,1024)
#define SOLVE_BASE 100            // solver CTAs: cb in [100,132)
#define NSOLVE 32
#define NPH1 258                  // phase-1 producers (non-solvers)
#define NPH2 190                  // phase-2 producers (late non-solvers + solvers)
#define HALF_ROWS 16384
#define W2SUM 538                 // ph2 weights: 32 solvers*2 + 158 others*3

// ------------- device scratch (no allocations; zero at load) -------------
__device__ __nv_bfloat16 g_R[(size_t)B_TOT * N_DIM];  // 32 MB bf16 r
__device__ float g_v[N_DIM];
__device__ float g_p[2][N_DIM];
__device__ float g_colsum[N_DIM];
__device__ double g_second;
__device__ unsigned g_bar_count, g_bar_gen;      // 32-CTA solve barrier
__device__ unsigned g_cntA, g_cntB;              // half-barrier arrive counters
__device__ unsigned g_done, g_vcnt, g_v_ready;

__constant__ int c_pi[NPAIRS] = {0,0,0,0,1,1,1,2,2,3};
__constant__ int c_pj[NPAIRS] = {0,1,2,3,1,2,3,2,3,3};

// ---- volatile acquire load: spin-safe (compiler cannot hoist/delete) ----
__device__ __forceinline__ unsigned ldv_acq(const unsigned* p) {
    unsigned v;
    asm volatile("ld.global.acquire.gpu.u32 %0, [%1];" : "=r"(v) : "l"(p) : "memory");
    return v;
}
// arrive: every thread fences its writes, then tid0 bumps the counter
__device__ __forceinline__ void arrive_cnt(unsigned* cnt) {
    __threadfence();
    __syncthreads();
    if (threadIdx.x == 0) atomicAdd(cnt, 1u);
}
__device__ __forceinline__ void wait_cnt(const unsigned* cnt, unsigned target) {
    if (threadIdx.x == 0) {
        while (ldv_acq(cnt) < target) __nanosleep(30);
        __threadfence();
    }
    __syncthreads();
}

// ---- grid barrier among the 32 solve CTAs ----
__device__ __forceinline__ void solve_barrier(unsigned target) {
    __syncthreads();
    if (threadIdx.x == 0) {
        __threadfence();
        if (atomicAdd(&g_bar_count, 1u) == NSOLVE - 1) {
            atomicExch(&g_bar_count, 0u);
            __threadfence();
            atomicExch(&g_bar_gen, target);
        } else {
            while (ldv_acq(&g_bar_gen) < target) __nanosleep(20);
        }
        __threadfence();
    }
    __syncthreads();
}

// -------------------------- GEMM helpers --------------------------
__device__ __forceinline__ void cp16(void* smem, const void* gmem) {
    unsigned saddr = (unsigned)__cvta_generic_to_shared(smem);
    asm volatile("cp.async.cg.shared.global [%0], [%1], 16;\n" :: "r"(saddr), "l"(gmem));
}
__device__ __forceinline__ void ldsm4t(unsigned& d0, unsigned& d1, unsigned& d2, unsigned& d3,
                                       const __nv_bfloat16* p) {
    unsigned a = (unsigned)__cvta_generic_to_shared(p);
    asm volatile("ldmatrix.sync.aligned.m8n8.x4.trans.shared.b16 {%0,%1,%2,%3}, [%4];\n"
                 : "=r"(d0), "=r"(d1), "=r"(d2), "=r"(d3) : "r"(a));
}
__device__ __forceinline__ void mma16816(float* c, const unsigned* a, const unsigned* b) {
    asm volatile(
        "mma.sync.aligned.m16n8k16.row.col.f32.bf16.bf16.f32 "
        "{%0,%1,%2,%3}, {%4,%5,%6,%7}, {%8,%9}, {%0,%1,%2,%3};\n"
        : "+f"(c[0]), "+f"(c[1]), "+f"(c[2]), "+f"(c[3])
        : "r"(a[0]), "r"(a[1]), "r"(a[2]), "r"(a[3]), "r"(b[0]), "r"(b[1]));
}

// ==================== one persistent kernel, pipelined halves ====================
__global__ void __launch_bounds__(256, 2) mono_k(const float* __restrict__ Gamma,
                                                 const float* __restrict__ SR,
                                                 const float* __restrict__ lsh,
                                                 const float* __restrict__ sig,
                                                 const int* __restrict__ kp,
                                                 float* __restrict__ out) {
    __shared__ __align__(16) __nv_bfloat16 smA[4][32][136];
    __shared__ __align__(16) __nv_bfloat16 smB[4][32][136];
    __shared__ float p_s[N_DIM];
    __shared__ double wsum[8];
    __shared__ bool is_last;

    const int tid  = threadIdx.x;
    const int lane = tid & 31, wid = tid >> 5;
    const int cb   = (int)blockIdx.x;
    const bool solver = (cb >= SOLVE_BASE) && (cb < SOLVE_BASE + NSOLVE);
    const bool early  = (cb < NEARLY);

    // ---------- pass1 production helper: r = exp(sig-lsh) -> bf16 g_R + colsums ----------
    auto produce = [&](int rbeg, int rend) {
        const int nchunk = (rend - rbeg) * 128;   // float4 chunks
        const int tc = tid & 127;                 // fixed column group
        float cs0 = 0.f, cs1 = 0.f, cs2 = 0.f, cs3 = 0.f;
#pragma unroll 4
        for (int idx = tid; idx < nchunk; idx += 256) {
            int r = rbeg + (idx >> 7);
            size_t off = (size_t)r * N_DIM + tc * 4;
            float4 a = __ldcs((const float4*)(lsh + off));
            float4 b = __ldcs((const float4*)(sig + off));
            float r0 = __expf(b.x - a.x), r1 = __expf(b.y - a.y);
            float r2 = __expf(b.z - a.z), r3 = __expf(b.w - a.w);
            cs0 += r0; cs1 += r1; cs2 += r2; cs3 += r3;
            __nv_bfloat162 h0 = __floats2bfloat162_rn(r0, r1);
            __nv_bfloat162 h1 = __floats2bfloat162_rn(r2, r3);
            uint2 u;
            u.x = *reinterpret_cast<unsigned*>(&h0);
            u.y = *reinterpret_cast<unsigned*>(&h1);
            *reinterpret_cast<uint2*>(&g_R[off]) = u;
        }
        atomicAdd(&g_colsum[tc * 4 + 0], cs0);
        atomicAdd(&g_colsum[tc * 4 + 1], cs1);
        atomicAdd(&g_colsum[tc * 4 + 2], cs2);
        atomicAdd(&g_colsum[tc * 4 + 3], cs3);
    };

    if (solver) {
        // ---------------- solve: v = Gamma^{-1} SR, Chebyshev, spec [1,5.5] ----------------
        const float lmin = 1.0f, lmax = 5.5f;
        const float theta = 0.5f * (lmax + lmin);
        const float delta = 0.5f * (lmax - lmin);
        const float sigma1 = theta / delta;
        float rho = 1.f / sigma1;
        const int row0 = (cb - SOLVE_BASE) * 16 + wid * 2;   // 2 rows per warp

        float4 gc[2][4];                          // register-cached Gamma rows
#pragma unroll
        for (int q = 0; q < 2; q++) {
            const float4* gr = (const float4*)(Gamma + (size_t)(row0 + q) * N_DIM);
#pragma unroll
            for (int tv = 0; tv < 4; tv++) gc[q][tv] = gr[lane + tv * 32];
        }
        float xv[2], rv[2], dv[2];
#pragma unroll
        for (int q = 0; q < 2; q++) {
            float b = SR[row0 + q];
            rv[q] = b; xv[q] = 0.f; dv[q] = b / theta;
            if (lane == 0) __stcg(&g_p[0][row0 + q], dv[q]);
        }
        unsigned gen = 0;
        for (int it = 0; it < SOLVE_ITERS; it++) {
            solve_barrier(++gen);
            int cur = it & 1;
            for (int j = tid; j < N_DIM; j += 256) p_s[j] = __ldcg(&g_p[cur][j]);
            __syncthreads();
#pragma unroll
            for (int q = 0; q < 2; q++) {
                const float4* pr = (const float4*)p_s;
                float acc = 0.f;
#pragma unroll
                for (int tv = 0; tv < 4; tv++) {
                    float4 g  = gc[q][tv];
                    float4 p4 = pr[lane + tv * 32];
                    acc += g.x * p4.x + g.y * p4.y + g.z * p4.z + g.w * p4.w;
                }
#pragma unroll
                for (int o = 16; o > 0; o >>= 1) acc += __shfl_xor_sync(0xffffffffu, acc, o);
                xv[q] += dv[q];
                rv[q] -= acc;
            }
            float rho_n = 1.f / (2.f * sigma1 - rho);
#pragma unroll
            for (int q = 0; q < 2; q++) {
                dv[q] = rho_n * rho * dv[q] + (2.f * rho_n / delta) * rv[q];
                if (lane == 0 && it + 1 < SOLVE_ITERS) __stcg(&g_p[cur ^ 1][row0 + q], dv[q]);
            }
            rho = rho_n;
            __syncthreads();
        }
        if (lane == 0) {
            __stcg(&g_v[row0], xv[0]);
            __stcg(&g_v[row0 + 1], xv[1]);
        }
        __threadfence();
        __syncthreads();
        if (tid == 0) {
            if (atomicAdd(&g_vcnt, 1u) == NSOLVE - 1) {
                __threadfence();
                atomicExch(&g_v_ready, 1u);
            }
        }
        // solvers produce a (weighted-small) phase-2 share, then sync B
        int w0 = (cb - SOLVE_BASE) * 2, w1 = w0 + 2;
        produce(HALF_ROWS + (int)(((long long)w0 * HALF_ROWS) / W2SUM),
                HALF_ROWS + (int)(((long long)w1 * HALF_ROWS) / W2SUM));
        arrive_cnt(&g_cntB);
        wait_cnt(&g_cntB, NPH2);
    } else if (early) {
        // early: phase-1 share, then wait for all of half 1
        int i = cb;                                // 0..99
        produce((int)(((long long)i * HALF_ROWS) / NPH1),
                (int)(((long long)(i + 1) * HALF_ROWS) / NPH1));
        arrive_cnt(&g_cntA);
        wait_cnt(&g_cntA, NPH1);
    } else {
        // late non-solver: ph1 share, arrive A (no wait), ph2 share, sync B
        int i = cb - NSOLVE;                       // 100..257
        produce((int)(((long long)i * HALF_ROWS) / NPH1),
                (int)(((long long)(i + 1) * HALF_ROWS) / NPH1));
        arrive_cnt(&g_cntA);
        int w0 = 64 + (cb - (SOLVE_BASE + NSOLVE)) * 3, w1 = w0 + 3;
        produce(HALF_ROWS + (int)(((long long)w0 * HALF_ROWS) / W2SUM),
                HALF_ROWS + (int)(((long long)w1 * HALF_ROWS) / W2SUM));
        arrive_cnt(&g_cntB);
        wait_cnt(&g_cntB, NPH2);
    }

    // ---------------- gemm slice: early in [0,512), late in [512,1024) ----------------
    int pair, sbeg, send;
    if (early) {
        pair = cb % NPAIRS;
        int e = cb / NPAIRS;                       // 0..9, ~51 stages each
        sbeg = (e * 512) / 10;
        send = ((e + 1) * 512) / 10;
    } else {
        int b = cb - NEARLY;
        pair = b % NPAIRS;
        int l = b / NPAIRS;                        // 0..18, ~27 stages each
        sbeg = 512 + (l * 512) / 19;
        send = 512 + ((l + 1) * 512) / 19;
    }
    const int ti = c_pi[pair] * 128, tj = c_pj[pair] * 128;
    const bool diag = (ti == tj);
    const int ns = send - sbeg;
    const int wi = wid >> 2, wj = wid & 3;         // warp tile 64(i) x 32(j)

    float acc[4][4][4];
#pragma unroll
    for (int a = 0; a < 4; a++)
#pragma unroll
        for (int b2 = 0; b2 < 4; b2++)
#pragma unroll
            for (int e = 0; e < 4; e++) acc[a][b2][e] = 0.f;

    auto load_stage = [&](int s, int buf) {
        int kbase = s * 32;
#pragma unroll
        for (int qq = 0; qq < 2; qq++) {
            int idx = tid + qq * 256;
            int row = idx >> 4, ch = idx & 15;
            const __nv_bfloat16* gbase = g_R + (size_t)(kbase + row) * N_DIM + ch * 8;
            cp16(&smA[buf][row][ch * 8], gbase + ti);
            if (!diag) cp16(&smB[buf][row][ch * 8], gbase + tj);
        }
    };

    load_stage(sbeg + 0, 0); asm volatile("cp.async.commit_group;\n");
    load_stage(sbeg + 1, 1); asm volatile("cp.async.commit_group;\n");
    load_stage(sbeg + 2, 2); asm volatile("cp.async.commit_group;\n");

    const __nv_bfloat16 (*smBsel)[32][136] = diag ? smA : smB;
    const int g = lane >> 3, r = lane & 7;
    for (int s = 0; s < ns; s++) {
        asm volatile("cp.async.wait_group 2;\n");   // stage s resident
        __syncthreads();                            // buf (s+3)&3 free for rewrite
        if (s + 3 < ns) load_stage(sbeg + s + 3, (s + 3) & 3);
        asm volatile("cp.async.commit_group;\n");
        const int buf = s & 3;
#pragma unroll
        for (int ks = 0; ks < 2; ks++) {
            int kk = ks * 16;
            unsigned afr[4][4], bfr[4][2];
#pragma unroll
            for (int mt = 0; mt < 4; mt++) {
                int i0 = wi * 64 + mt * 16;
                const __nv_bfloat16* p = &smA[buf][kk + ((g >> 1) << 3) + r][i0 + ((g & 1) << 3)];
                ldsm4t(afr[mt][0], afr[mt][1], afr[mt][2], afr[mt][3], p);
            }
#pragma unroll
            for (int n2 = 0; n2 < 2; n2++) {
                int j0 = wj * 32 + n2 * 16;
                const __nv_bfloat16* p = &smBsel[buf][kk + ((g & 1) << 3) + r][j0 + ((g >> 1) << 3)];
                unsigned d0, d1, d2, d3;
                ldsm4t(d0, d1, d2, d3, p);
                bfr[n2 * 2][0] = d0; bfr[n2 * 2][1] = d1;
                bfr[n2 * 2 + 1][0] = d2; bfr[n2 * 2 + 1][1] = d3;
            }
#pragma unroll
            for (int mt = 0; mt < 4; mt++)
#pragma unroll
                for (int nt = 0; nt < 4; nt++) mma16816(acc[mt][nt], afr[mt], bfr[nt]);
        }
    }

    // ---- v (ready long before any CTA reaches here; proven spin) ----
    if (tid == 0) { while (ldv_acq(&g_v_ready) == 0u) __nanosleep(20); }
    __syncthreads();
    for (int j = tid; j < N_DIM; j += 256) p_s[j] = __ldcg(&g_v[j]);
    __syncthreads();

    // epilogue: partial = sum Gamma_ij v_i v_j C_ij over this CTA's tile
    float partf = 0.f;
#pragma unroll
    for (int mt = 0; mt < 4; mt++) {
        int ibase = ti + wi * 64 + mt * 16 + (lane >> 2);
#pragma unroll
        for (int nt = 0; nt < 4; nt++) {
            int jbase = tj + wj * 32 + nt * 8 + 2 * (lane & 3);
#pragma unroll
            for (int e = 0; e < 4; e++) {
                int i = ibase + ((e >> 1) << 3);
                int j = jbase + (e & 1);
                partf += acc[mt][nt][e] * Gamma[(size_t)i * N_DIM + j] * p_s[i] * p_s[j];
            }
        }
    }
#pragma unroll
    for (int o = 16; o > 0; o >>= 1) partf += __shfl_xor_sync(0xffffffffu, partf, o);
    if (lane == 0) wsum[wid] = (double)partf;
    __syncthreads();
    if (tid == 0) {
        double sv = 0.0;
        for (int x = 0; x < 8; x++) sv += wsum[x];
        if (ti != tj) sv *= 2.0;   // off-diagonal tiles counted twice (symmetry)
        atomicAdd(&g_second, sv);
        __threadfence();
        unsigned d = atomicAdd(&g_done, 1u);
        is_last = (d == NTOT - 1);
    }
    __syncthreads();

    // ---------------- last CTA finalizes + resets for next replay ----------------
    if (is_last) {
        double term = 0.0;
        for (int j = tid; j < N_DIM; j += 256)
            term += (double)__ldcg(&g_colsum[j]) * (double)p_s[j] * (double)SR[j];
#pragma unroll
        for (int o = 16; o > 0; o >>= 1) term += __shfl_xor_sync(0xffffffffu, term, o);
        if (lane == 0) wsum[wid] = term;
        __syncthreads();
        if (tid == 0) {
            double sf = 0.0;
            for (int x = 0; x < 8; x++) sf += wsum[x];
            double sec = atomicAdd(&g_second, 0.0);
            double k = (double)kp[0];
            out[0] = (float)((0.5 * sec - sf) / ((double)B_TOT * k));
        }
        __syncthreads();
        for (int j = tid; j < N_DIM; j += 256) g_colsum[j] = 0.f;
        if (tid == 0) {
            g_second = 0.0;
            g_done = 0u; g_vcnt = 0u; g_v_ready = 0u;
            g_bar_count = 0u; g_bar_gen = 0u;
            g_cntA = 0u; g_cntB = 0u;
        }
    }
}

// ------------------------------ launch ------------------------------
extern "C" void kernel_launch(void* const* d_in, const int* in_sizes, int n_in,
                              void* d_out, int out_size) {
    const float* lsh = (const float*)d_in[0];
    const float* sig = (const float*)d_in[1];
    const float* SR  = (const float*)d_in[2];
    const float* Gam = (const float*)d_in[3];
    const int*   kp  = (const int*)d_in[4];

    mono_k<<<NTOT, 256>>>(Gam, SR, lsh, sig, kp, (float*)d_out);
}

// round 15
// speedup vs baseline: 1.1897x; 1.1818x over previous
#include <cuda_runtime.h>
#include <cuda_bf16.h>
#include <stdint.h>

#define B_TOT 32768
#define N_DIM 512
#define SOLVE_ITERS 10
#define NSOLVE 32
#define NTOT 292                     // 2 pairs*30 + 8 pairs*29 slices; == capacity @2 CTA/SM
#define NPAIRS 10
#define TOT_STAGES (B_TOT / 32)      // 1024
#define WSUM 812                     // pass1 row weights: 32 solvers*1 + 260 others*3

// ------------- device scratch (no allocations; zero at load) -------------
__device__ __nv_bfloat16 g_R[(size_t)B_TOT * N_DIM];  // 32 MB bf16 r
__device__ float g_v[N_DIM];
__device__ float g_p[2][N_DIM];
__device__ float g_colsum[N_DIM];
__device__ double g_second;
__device__ unsigned g_bar_count, g_bar_gen;      // 32-CTA solve barrier
__device__ unsigned g_gbar_count, g_gbar_gen;    // 292-CTA global barrier
__device__ unsigned g_done;

__constant__ int c_pi[NPAIRS] = {0,0,0,0,1,1,1,2,2,3};
__constant__ int c_pj[NPAIRS] = {0,1,2,3,1,2,3,2,3,3};

// ---- volatile acquire load: spin-safe (compiler cannot hoist/delete) ----
__device__ __forceinline__ unsigned ldv_acq(const unsigned* p) {
    unsigned v;
    asm volatile("ld.global.acquire.gpu.u32 %0, [%1];" : "=r"(v) : "l"(p) : "memory");
    return v;
}

// ---- N-CTA barrier: all threads release-fence, tid0 arrives + spins ----
__device__ __forceinline__ void barrier_n(unsigned* cnt, unsigned* gen,
                                          unsigned n, unsigned target) {
    __threadfence();                 // every thread releases its own writes
    __syncthreads();
    if (threadIdx.x == 0) {
        if (atomicAdd(cnt, 1u) == n - 1) {
            atomicExch(cnt, 0u);
            __threadfence();
            atomicExch(gen, target);
        } else {
            while (ldv_acq(gen) < target) __nanosleep(20);
        }
        __threadfence();
    }
    __syncthreads();
}

// -------------------------- GEMM helpers --------------------------
__device__ __forceinline__ void cp16(void* smem, const void* gmem) {
    unsigned saddr = (unsigned)__cvta_generic_to_shared(smem);
    asm volatile("cp.async.cg.shared.global [%0], [%1], 16;\n" :: "r"(saddr), "l"(gmem));
}
__device__ __forceinline__ void ldsm4t(unsigned& d0, unsigned& d1, unsigned& d2, unsigned& d3,
                                       const __nv_bfloat16* p) {
    unsigned a = (unsigned)__cvta_generic_to_shared(p);
    asm volatile("ldmatrix.sync.aligned.m8n8.x4.trans.shared.b16 {%0,%1,%2,%3}, [%4];\n"
                 : "=r"(d0), "=r"(d1), "=r"(d2), "=r"(d3) : "r"(a));
}
__device__ __forceinline__ void mma16816(float* c, const unsigned* a, const unsigned* b) {
    asm volatile(
        "mma.sync.aligned.m16n8k16.row.col.f32.bf16.bf16.f32 "
        "{%0,%1,%2,%3}, {%4,%5,%6,%7}, {%8,%9}, {%0,%1,%2,%3};\n"
        : "+f"(c[0]), "+f"(c[1]), "+f"(c[2]), "+f"(c[3])
        : "r"(a[0]), "r"(a[1]), "r"(a[2]), "r"(a[3]), "r"(b[0]), "r"(b[1]));
}

// ==================== the whole problem in ONE kernel (R11 structure) ====================
// Phase A: CTAs 0..31 Chebyshev-solve v = Gamma^{-1}SR (spec [1,5.5]) then a
//          small pass1 share; CTAs 32.. big pass1 shares.
//          pass1 now front-batches 16 float4 LDGs per thread (MLP fix).
// Global 292-CTA barrier.
// Phase B: syrk S = R^T R via mma.bf16; epilogue folds sum Gamma_ij v_i v_j S_ij.
// Phase C: last CTA emits scalar, resets state for next graph replay.
__global__ void __launch_bounds__(256, 2) mono_k(const float* __restrict__ Gamma,
                                                 const float* __restrict__ SR,
                                                 const float* __restrict__ lsh,
                                                 const float* __restrict__ sig,
                                                 const int* __restrict__ kp,
                                                 float* __restrict__ out) {
    __shared__ __align__(16) __nv_bfloat16 smA[4][32][136];
    __shared__ __align__(16) __nv_bfloat16 smB[4][32][136];
    __shared__ float p_s[N_DIM];
    __shared__ double wsum[8];
    __shared__ bool is_last;

    const int tid  = threadIdx.x;
    const int lane = tid & 31, wid = tid >> 5;
    const int cb   = (int)blockIdx.x;

    // ---------------- Phase A1: solve (CTAs 0..31) ----------------
    if (cb < NSOLVE) {
        const float lmin = 1.0f, lmax = 5.5f;
        const float theta = 0.5f * (lmax + lmin);
        const float delta = 0.5f * (lmax - lmin);
        const float sigma1 = theta / delta;
        float rho = 1.f / sigma1;
        const int row0 = cb * 16 + wid * 2;       // 2 rows per warp

        float4 gc[2][4];                          // register-cached Gamma rows
#pragma unroll
        for (int q = 0; q < 2; q++) {
            const float4* gr = (const float4*)(Gamma + (size_t)(row0 + q) * N_DIM);
#pragma unroll
            for (int tv = 0; tv < 4; tv++) gc[q][tv] = gr[lane + tv * 32];
        }
        float xv[2], rv[2], dv[2];
#pragma unroll
        for (int q = 0; q < 2; q++) {
            float b = SR[row0 + q];
            rv[q] = b; xv[q] = 0.f; dv[q] = b / theta;
            if (lane == 0) __stcg(&g_p[0][row0 + q], dv[q]);
        }
        unsigned gen = 0;
        for (int it = 0; it < SOLVE_ITERS; it++) {
            barrier_n(&g_bar_count, &g_bar_gen, NSOLVE, ++gen);
            int cur = it & 1;
            for (int j = tid; j < N_DIM; j += 256) p_s[j] = __ldcg(&g_p[cur][j]);
            __syncthreads();
#pragma unroll
            for (int q = 0; q < 2; q++) {
                const float4* pr = (const float4*)p_s;
                float acc = 0.f;
#pragma unroll
                for (int tv = 0; tv < 4; tv++) {
                    float4 g  = gc[q][tv];
                    float4 p4 = pr[lane + tv * 32];
                    acc += g.x * p4.x + g.y * p4.y + g.z * p4.z + g.w * p4.w;
                }
#pragma unroll
                for (int o = 16; o > 0; o >>= 1) acc += __shfl_xor_sync(0xffffffffu, acc, o);
                xv[q] += dv[q];
                rv[q] -= acc;
            }
            float rho_n = 1.f / (2.f * sigma1 - rho);
#pragma unroll
            for (int q = 0; q < 2; q++) {
                dv[q] = rho_n * rho * dv[q] + (2.f * rho_n / delta) * rv[q];
                if (lane == 0 && it + 1 < SOLVE_ITERS) __stcg(&g_p[cur ^ 1][row0 + q], dv[q]);
            }
            rho = rho_n;
            __syncthreads();
        }
        if (lane == 0) {
            __stcg(&g_v[row0], xv[0]);
            __stcg(&g_v[row0 + 1], xv[1]);
        }
        __syncthreads();
    }

    // ---------------- Phase A2: pass1 (all CTAs, weighted rows) ----------------
    // MLP fix: front-batch 8 row-chunks (16 float4 LDGs) per thread before compute.
    {
        const int w0 = (cb < NSOLVE) ? cb : NSOLVE + (cb - NSOLVE) * 3;
        const int w1 = (cb < NSOLVE) ? cb + 1 : NSOLVE + (cb - NSOLVE + 1) * 3;
        const int rbeg = (int)(((long long)w0 * B_TOT) / WSUM);
        const int rend = (int)(((long long)w1 * B_TOT) / WSUM);
        const int nchunk = (rend - rbeg) * 128;   // float4 chunks
        const int tc = tid & 127;                 // fixed column group
        const size_t colOff = (size_t)tc * 4;
        float cs0 = 0.f, cs1 = 0.f, cs2 = 0.f, cs3 = 0.f;

        int base = tid;
        for (; base + 256 * 7 < nchunk; base += 256 * 8) {
            float4 av[8], bv[8];
#pragma unroll
            for (int u = 0; u < 8; u++) {                 // 16 LDG.128 in flight
                int idx = base + (u << 8);
                size_t off = (size_t)(rbeg + (idx >> 7)) * N_DIM + colOff;
                av[u] = __ldcs((const float4*)(lsh + off));
                bv[u] = __ldcs((const float4*)(sig + off));
            }
#pragma unroll
            for (int u = 0; u < 8; u++) {
                int idx = base + (u << 8);
                size_t off = (size_t)(rbeg + (idx >> 7)) * N_DIM + colOff;
                float r0 = __expf(bv[u].x - av[u].x), r1 = __expf(bv[u].y - av[u].y);
                float r2 = __expf(bv[u].z - av[u].z), r3 = __expf(bv[u].w - av[u].w);
                cs0 += r0; cs1 += r1; cs2 += r2; cs3 += r3;
                __nv_bfloat162 h0 = __floats2bfloat162_rn(r0, r1);
                __nv_bfloat162 h1 = __floats2bfloat162_rn(r2, r3);
                uint2 u2;
                u2.x = *reinterpret_cast<unsigned*>(&h0);
                u2.y = *reinterpret_cast<unsigned*>(&h1);
                *reinterpret_cast<uint2*>(&g_R[off]) = u2;
            }
        }
        for (int idx = base; idx < nchunk; idx += 256) {  // tail
            size_t off = (size_t)(rbeg + (idx >> 7)) * N_DIM + colOff;
            float4 a = __ldcs((const float4*)(lsh + off));
            float4 b = __ldcs((const float4*)(sig + off));
            float r0 = __expf(b.x - a.x), r1 = __expf(b.y - a.y);
            float r2 = __expf(b.z - a.z), r3 = __expf(b.w - a.w);
            cs0 += r0; cs1 += r1; cs2 += r2; cs3 += r3;
            __nv_bfloat162 h0 = __floats2bfloat162_rn(r0, r1);
            __nv_bfloat162 h1 = __floats2bfloat162_rn(r2, r3);
            uint2 u2;
            u2.x = *reinterpret_cast<unsigned*>(&h0);
            u2.y = *reinterpret_cast<unsigned*>(&h1);
            *reinterpret_cast<uint2*>(&g_R[off]) = u2;
        }
        atomicAdd(&g_colsum[tc * 4 + 0], cs0);
        atomicAdd(&g_colsum[tc * 4 + 1], cs1);
        atomicAdd(&g_colsum[tc * 4 + 2], cs2);
        atomicAdd(&g_colsum[tc * 4 + 3], cs3);
    }

    // ---------------- global barrier: g_R and g_v are complete ----------------
    barrier_n(&g_gbar_count, &g_gbar_gen, NTOT, 1u);

    // ---------------- Phase B: syrk over (pair, k-slice) ----------------
    const int pair = cb % NPAIRS;
    const int q    = cb / NPAIRS;                 // 0..29 (29 only for pairs 0,1)
    const int SP   = (pair < 2) ? 30 : 29;
    const int sbeg = (q * TOT_STAGES) / SP;
    const int send = ((q + 1) * TOT_STAGES) / SP;
    const int ns   = send - sbeg;                 // 34..36

    const int ti = c_pi[pair] * 128, tj = c_pj[pair] * 128;
    const bool diag = (ti == tj);
    const int wi = wid >> 2, wj = wid & 3;        // warp tile 64(i) x 32(j)

    float acc[4][4][4];
#pragma unroll
    for (int a = 0; a < 4; a++)
#pragma unroll
        for (int b2 = 0; b2 < 4; b2++)
#pragma unroll
            for (int e = 0; e < 4; e++) acc[a][b2][e] = 0.f;

    auto load_stage = [&](int s, int buf) {
        int kbase = s * 32;
#pragma unroll
        for (int qq = 0; qq < 2; qq++) {
            int idx = tid + qq * 256;
            int row = idx >> 4, ch = idx & 15;
            const __nv_bfloat16* gbase = g_R + (size_t)(kbase + row) * N_DIM + ch * 8;
            cp16(&smA[buf][row][ch * 8], gbase + ti);
            if (!diag) cp16(&smB[buf][row][ch * 8], gbase + tj);
        }
    };

    load_stage(sbeg + 0, 0); asm volatile("cp.async.commit_group;\n");
    load_stage(sbeg + 1, 1); asm volatile("cp.async.commit_group;\n");
    load_stage(sbeg + 2, 2); asm volatile("cp.async.commit_group;\n");

    const __nv_bfloat16 (*smBsel)[32][136] = diag ? smA : smB;
    const int g = lane >> 3, r = lane & 7;
    for (int s = 0; s < ns; s++) {
        asm volatile("cp.async.wait_group 2;\n");   // stage s resident
        __syncthreads();                            // buf (s+3)&3 free for rewrite
        if (s + 3 < ns) load_stage(sbeg + s + 3, (s + 3) & 3);
        asm volatile("cp.async.commit_group;\n");   // empty commit at tail keeps count
        const int buf = s & 3;
#pragma unroll
        for (int ks = 0; ks < 2; ks++) {
            int kk = ks * 16;
            unsigned afr[4][4], bfr[4][2];
#pragma unroll
            for (int mt = 0; mt < 4; mt++) {
                int i0 = wi * 64 + mt * 16;
                const __nv_bfloat16* p = &smA[buf][kk + ((g >> 1) << 3) + r][i0 + ((g & 1) << 3)];
                ldsm4t(afr[mt][0], afr[mt][1], afr[mt][2], afr[mt][3], p);
            }
#pragma unroll
            for (int n2 = 0; n2 < 2; n2++) {
                int j0 = wj * 32 + n2 * 16;
                const __nv_bfloat16* p = &smBsel[buf][kk + ((g & 1) << 3) + r][j0 + ((g >> 1) << 3)];
                unsigned d0, d1, d2, d3;
                ldsm4t(d0, d1, d2, d3, p);
                bfr[n2 * 2][0] = d0; bfr[n2 * 2][1] = d1;
                bfr[n2 * 2 + 1][0] = d2; bfr[n2 * 2 + 1][1] = d3;
            }
#pragma unroll
            for (int mt = 0; mt < 4; mt++)
#pragma unroll
                for (int nt = 0; nt < 4; nt++) mma16816(acc[mt][nt], afr[mt], bfr[nt]);
        }
    }

    // ---- stage v into smem (complete since the global barrier) ----
    for (int j = tid; j < N_DIM; j += 256) p_s[j] = __ldcg(&g_v[j]);
    __syncthreads();

    // epilogue: partial = sum Gamma_ij v_i v_j C_ij over this CTA's tile
    float partf = 0.f;
#pragma unroll
    for (int mt = 0; mt < 4; mt++) {
        int ibase = ti + wi * 64 + mt * 16 + (lane >> 2);
#pragma unroll
        for (int nt = 0; nt < 4; nt++) {
            int jbase = tj + wj * 32 + nt * 8 + 2 * (lane & 3);
#pragma unroll
            for (int e = 0; e < 4; e++) {
                int i = ibase + ((e >> 1) << 3);
                int j = jbase + (e & 1);
                partf += acc[mt][nt][e] * Gamma[(size_t)i * N_DIM + j] * p_s[i] * p_s[j];
            }
        }
    }
#pragma unroll
    for (int o = 16; o > 0; o >>= 1) partf += __shfl_xor_sync(0xffffffffu, partf, o);
    if (lane == 0) wsum[wid] = (double)partf;
    __syncthreads();
    if (tid == 0) {
        double sv = 0.0;
        for (int x = 0; x < 8; x++) sv += wsum[x];
        if (ti != tj) sv *= 2.0;   // off-diagonal tiles counted twice (symmetry)
        atomicAdd(&g_second, sv);
        __threadfence();
        unsigned d = atomicAdd(&g_done, 1u);
        is_last = (d == NTOT - 1);
    }
    __syncthreads();

    // ---------------- Phase C: last CTA finalizes + resets ----------------
    if (is_last) {
        double term = 0.0;
        for (int j = tid; j < N_DIM; j += 256)
            term += (double)__ldcg(&g_colsum[j]) * (double)p_s[j] * (double)SR[j];
#pragma unroll
        for (int o = 16; o > 0; o >>= 1) term += __shfl_xor_sync(0xffffffffu, term, o);
        if (lane == 0) wsum[wid] = term;
        __syncthreads();
        if (tid == 0) {
            double sf = 0.0;
            for (int x = 0; x < 8; x++) sf += wsum[x];
            double sec = atomicAdd(&g_second, 0.0);   // writers fenced before g_done
            double k = (double)kp[0];
            out[0] = (float)((0.5 * sec - sf) / ((double)B_TOT * k));
        }
        __syncthreads();
        // self-clean device state for the next graph replay
        for (int j = tid; j < N_DIM; j += 256) g_colsum[j] = 0.f;
        if (tid == 0) {
            g_second = 0.0;
            g_done = 0u;
            g_bar_count = 0u; g_bar_gen = 0u;
            g_gbar_count = 0u; g_gbar_gen = 0u;
        }
    }
}

// ------------------------------ launch ------------------------------
extern "C" void kernel_launch(void* const* d_in, const int* in_sizes, int n_in,
                              void* d_out, int out_size) {
    const float* lsh = (const float*)d_in[0];
    const float* sig = (const float*)d_in[1];
    const float* SR  = (const float*)d_in[2];
    const float* Gam = (const float*)d_in[3];
    const int*   kp  = (const int*)d_in[4];

    mono_k<<<NTOT, 256>>>(Gam, SR, lsh, sig, kp, (float*)d_out);
}

// round 16
// speedup vs baseline: 1.3279x; 1.1161x over previous
#include <cuda_runtime.h>
#include <cuda_bf16.h>
#include <stdint.h>

#define B_TOT 32768
#define N_DIM 512
#define SOLVE_ITERS 10
#define NSOLVE 32
#define NTOT 290                     // 29 teams * 10 pairs; <=296 resident @2 CTA/SM
#define NPAIRS 10
#define S1 768                       // cohort-1 stage range [0,768); cohort-2 [768,1024)
#define ROWS1 (S1 * 32)              // 24576 rows produced in phase 1
#define NPROD1 258                   // phase-1 producers: CTAs 0..257
#define NPROD2 90                    // phase-2 producers: CTAs 200..289
#define SOLVE_BASE 258               // solver CTAs: 258..289 (cohort 2, latest teams)

// ------------- device scratch (no allocations; zero at load) -------------
__device__ __nv_bfloat16 g_R[(size_t)B_TOT * N_DIM];  // 32 MB bf16 r
__device__ float g_v[N_DIM];
__device__ float g_p[2][N_DIM];
__device__ float g_colsum[N_DIM];
__device__ double g_second;
__device__ unsigned g_bar_count, g_bar_gen;      // 32-CTA solve barrier
__device__ unsigned g_cntA, g_cntB;              // phase-completion counters
__device__ unsigned g_done, g_vcnt, g_v_ready;

__constant__ int c_pi[NPAIRS] = {0,0,0,0,1,1,1,2,2,3};
__constant__ int c_pj[NPAIRS] = {0,1,2,3,1,2,3,2,3,3};

// ---- volatile acquire load: spin-safe (compiler cannot hoist/delete) ----
__device__ __forceinline__ unsigned ldv_acq(const unsigned* p) {
    unsigned v;
    asm volatile("ld.global.acquire.gpu.u32 %0, [%1];" : "=r"(v) : "l"(p) : "memory");
    return v;
}
// arrive: every thread release-fences its writes, then tid0 bumps the counter
__device__ __forceinline__ void arrive_cnt(unsigned* cnt) {
    __threadfence();
    __syncthreads();
    if (threadIdx.x == 0) atomicAdd(cnt, 1u);
}
__device__ __forceinline__ void wait_cnt(const unsigned* cnt, unsigned target) {
    if (threadIdx.x == 0) {
        while (ldv_acq(cnt) < target) __nanosleep(30);
        __threadfence();
    }
    __syncthreads();
}
// ---- grid barrier among the 32 solve CTAs ----
__device__ __forceinline__ void solve_barrier(unsigned target) {
    __syncthreads();
    if (threadIdx.x == 0) {
        __threadfence();
        if (atomicAdd(&g_bar_count, 1u) == NSOLVE - 1) {
            atomicExch(&g_bar_count, 0u);
            __threadfence();
            atomicExch(&g_bar_gen, target);
        } else {
            while (ldv_acq(&g_bar_gen) < target) __nanosleep(20);
        }
        __threadfence();
    }
    __syncthreads();
}

// -------------------------- GEMM helpers --------------------------
__device__ __forceinline__ void cp16(void* smem, const void* gmem) {
    unsigned saddr = (unsigned)__cvta_generic_to_shared(smem);
    asm volatile("cp.async.cg.shared.global [%0], [%1], 16;\n" :: "r"(saddr), "l"(gmem));
}
__device__ __forceinline__ void ldsm4t(unsigned& d0, unsigned& d1, unsigned& d2, unsigned& d3,
                                       const __nv_bfloat16* p) {
    unsigned a = (unsigned)__cvta_generic_to_shared(p);
    asm volatile("ldmatrix.sync.aligned.m8n8.x4.trans.shared.b16 {%0,%1,%2,%3}, [%4];\n"
                 : "=r"(d0), "=r"(d1), "=r"(d2), "=r"(d3) : "r"(a));
}
__device__ __forceinline__ void mma16816(float* c, const unsigned* a, const unsigned* b) {
    asm volatile(
        "mma.sync.aligned.m16n8k16.row.col.f32.bf16.bf16.f32 "
        "{%0,%1,%2,%3}, {%4,%5,%6,%7}, {%8,%9}, {%0,%1,%2,%3};\n"
        : "+f"(c[0]), "+f"(c[1]), "+f"(c[2]), "+f"(c[3])
        : "r"(a[0]), "r"(a[1]), "r"(a[2]), "r"(a[3]), "r"(b[0]), "r"(b[1]));
}

// ==================== one persistent kernel, 2-cohort pipelined ====================
// CTAs 0..199   : produce phase-1 rows (stride-258) -> arrive A -> wait A -> gemm [0,768)
// CTAs 200..257 : phase-1 share -> arrive A -> phase-2 share -> arrive B -> wait B -> gemm [768,1024)
// CTAs 258..289 : Chebyshev solve (hidden under phase 1) -> phase-2 share -> arrive B -> wait B -> gemm
// Epilogue folds sum_ij Gamma_ij v_i v_j S_ij; last CTA emits scalar + resets state.
__global__ void __launch_bounds__(256, 2) mono_k(const float* __restrict__ Gamma,
                                                 const float* __restrict__ SR,
                                                 const float* __restrict__ lsh,
                                                 const float* __restrict__ sig,
                                                 const int* __restrict__ kp,
                                                 float* __restrict__ out) {
    __shared__ __align__(16) __nv_bfloat16 smA[4][32][136];
    __shared__ __align__(16) __nv_bfloat16 smB[4][32][136];
    __shared__ float p_s[N_DIM];
    __shared__ double wsum[8];
    __shared__ bool is_last;

    const int tid  = threadIdx.x;
    const int lane = tid & 31, wid = tid >> 5;
    const int cb   = (int)blockIdx.x;

    // ---------- producer: r = exp(sig-lsh) -> bf16 g_R + colsums (strided rows) ----------
    auto produce = [&](int start, int stride, int limit) {
        const int my_rows = (limit - start + stride - 1) / stride;
        const int tc = tid & 127;                 // column group (4 cols)
        const int half = tid >> 7;                // 0/1: two rows per u-step
        const size_t colOff = (size_t)tc * 4;
        float cs0 = 0.f, cs1 = 0.f, cs2 = 0.f, cs3 = 0.f;
        for (int jb = 0; jb < my_rows; jb += 16) {
            float4 av[8], bv[8];
            int rw[8]; bool va[8];
#pragma unroll
            for (int u = 0; u < 8; u++) {         // 16 LDG.128 in flight per thread
                int j = jb + u * 2 + half;
                bool v = (j < my_rows);
                int row = v ? (start + j * stride) : start;
                rw[u] = row; va[u] = v;
                size_t off = (size_t)row * N_DIM + colOff;
                av[u] = __ldcs((const float4*)(lsh + off));
                bv[u] = __ldcs((const float4*)(sig + off));
            }
#pragma unroll
            for (int u = 0; u < 8; u++) {
                if (!va[u]) continue;
                float r0 = __expf(bv[u].x - av[u].x), r1 = __expf(bv[u].y - av[u].y);
                float r2 = __expf(bv[u].z - av[u].z), r3 = __expf(bv[u].w - av[u].w);
                cs0 += r0; cs1 += r1; cs2 += r2; cs3 += r3;
                __nv_bfloat162 h0 = __floats2bfloat162_rn(r0, r1);
                __nv_bfloat162 h1 = __floats2bfloat162_rn(r2, r3);
                uint2 u2;
                u2.x = *reinterpret_cast<unsigned*>(&h0);
                u2.y = *reinterpret_cast<unsigned*>(&h1);
                *reinterpret_cast<uint2*>(&g_R[(size_t)rw[u] * N_DIM + colOff]) = u2;
            }
        }
        atomicAdd(&g_colsum[tc * 4 + 0], cs0);
        atomicAdd(&g_colsum[tc * 4 + 1], cs1);
        atomicAdd(&g_colsum[tc * 4 + 2], cs2);
        atomicAdd(&g_colsum[tc * 4 + 3], cs3);
    };

    if (cb >= SOLVE_BASE) {
        // ---------------- solve: v = Gamma^{-1} SR, Chebyshev, spec [1,5.5] ----------------
        const float lmin = 1.0f, lmax = 5.5f;
        const float theta = 0.5f * (lmax + lmin);
        const float delta = 0.5f * (lmax - lmin);
        const float sigma1 = theta / delta;
        float rho = 1.f / sigma1;
        const int row0 = (cb - SOLVE_BASE) * 16 + wid * 2;   // 2 rows per warp

        float4 gc[2][4];                          // register-cached Gamma rows
#pragma unroll
        for (int q = 0; q < 2; q++) {
            const float4* gr = (const float4*)(Gamma + (size_t)(row0 + q) * N_DIM);
#pragma unroll
            for (int tv = 0; tv < 4; tv++) gc[q][tv] = gr[lane + tv * 32];
        }
        float xv[2], rv[2], dv[2];
#pragma unroll
        for (int q = 0; q < 2; q++) {
            float b = SR[row0 + q];
            rv[q] = b; xv[q] = 0.f; dv[q] = b / theta;
            if (lane == 0) __stcg(&g_p[0][row0 + q], dv[q]);
        }
        unsigned gen = 0;
        for (int it = 0; it < SOLVE_ITERS; it++) {
            solve_barrier(++gen);
            int cur = it & 1;
            for (int j = tid; j < N_DIM; j += 256) p_s[j] = __ldcg(&g_p[cur][j]);
            __syncthreads();
#pragma unroll
            for (int q = 0; q < 2; q++) {
                const float4* pr = (const float4*)p_s;
                float acc = 0.f;
#pragma unroll
                for (int tv = 0; tv < 4; tv++) {
                    float4 g  = gc[q][tv];
                    float4 p4 = pr[lane + tv * 32];
                    acc += g.x * p4.x + g.y * p4.y + g.z * p4.z + g.w * p4.w;
                }
#pragma unroll
                for (int o = 16; o > 0; o >>= 1) acc += __shfl_xor_sync(0xffffffffu, acc, o);
                xv[q] += dv[q];
                rv[q] -= acc;
            }
            float rho_n = 1.f / (2.f * sigma1 - rho);
#pragma unroll
            for (int q = 0; q < 2; q++) {
                dv[q] = rho_n * rho * dv[q] + (2.f * rho_n / delta) * rv[q];
                if (lane == 0 && it + 1 < SOLVE_ITERS) __stcg(&g_p[cur ^ 1][row0 + q], dv[q]);
            }
            rho = rho_n;
            __syncthreads();
        }
        if (lane == 0) {
            __stcg(&g_v[row0], xv[0]);
            __stcg(&g_v[row0 + 1], xv[1]);
        }
        __threadfence();
        __syncthreads();
        if (tid == 0) {
            if (atomicAdd(&g_vcnt, 1u) == NSOLVE - 1) {
                __threadfence();
                atomicExch(&g_v_ready, 1u);
            }
        }
        // solvers produce a phase-2 share, then sync B
        produce(ROWS1 + (cb - 200), NPROD2, B_TOT);
        arrive_cnt(&g_cntB);
        wait_cnt(&g_cntB, NPROD2);
    } else if (cb >= 200) {
        // cohort-2 non-solver: ph1 share -> arrive A -> ph2 share -> sync B
        produce(cb, NPROD1, ROWS1);
        arrive_cnt(&g_cntA);
        produce(ROWS1 + (cb - 200), NPROD2, B_TOT);
        arrive_cnt(&g_cntB);
        wait_cnt(&g_cntB, NPROD2);
    } else {
        // cohort-1: ph1 share -> sync A
        produce(cb, NPROD1, ROWS1);
        arrive_cnt(&g_cntA);
        wait_cnt(&g_cntA, NPROD1);
    }

    // ---------------- gemm slice ----------------
    int pair, sbeg, send;
    if (cb < 200) {
        int t = cb / 10; pair = cb % 10;
        sbeg = (t * S1) / 20;
        send = ((t + 1) * S1) / 20;                // ~38 stages
    } else {
        int b = cb - 200;
        int t = b / 10; pair = b % 10;
        sbeg = S1 + (t * (1024 - S1)) / 9;
        send = S1 + ((t + 1) * (1024 - S1)) / 9;   // ~28 stages
    }
    const int ti = c_pi[pair] * 128, tj = c_pj[pair] * 128;
    const bool diag = (ti == tj);
    const int ns = send - sbeg;
    const int wi = wid >> 2, wj = wid & 3;         // warp tile 64(i) x 32(j)

    float acc[4][4][4];
#pragma unroll
    for (int a = 0; a < 4; a++)
#pragma unroll
        for (int b2 = 0; b2 < 4; b2++)
#pragma unroll
            for (int e = 0; e < 4; e++) acc[a][b2][e] = 0.f;

    auto load_stage = [&](int s, int buf) {
        int kbase = s * 32;
#pragma unroll
        for (int qq = 0; qq < 2; qq++) {
            int idx = tid + qq * 256;
            int row = idx >> 4, ch = idx & 15;
            const __nv_bfloat16* gbase = g_R + (size_t)(kbase + row) * N_DIM + ch * 8;
            cp16(&smA[buf][row][ch * 8], gbase + ti);
            if (!diag) cp16(&smB[buf][row][ch * 8], gbase + tj);
        }
    };

    load_stage(sbeg + 0, 0); asm volatile("cp.async.commit_group;\n");
    load_stage(sbeg + 1, 1); asm volatile("cp.async.commit_group;\n");
    load_stage(sbeg + 2, 2); asm volatile("cp.async.commit_group;\n");

    const __nv_bfloat16 (*smBsel)[32][136] = diag ? smA : smB;
    const int g = lane >> 3, r = lane & 7;
    for (int s = 0; s < ns; s++) {
        asm volatile("cp.async.wait_group 2;\n");   // stage s resident
        __syncthreads();                            // buf (s+3)&3 free for rewrite
        if (s + 3 < ns) load_stage(sbeg + s + 3, (s + 3) & 3);
        asm volatile("cp.async.commit_group;\n");   // empty commit at tail keeps count
        const int buf = s & 3;
#pragma unroll
        for (int ks = 0; ks < 2; ks++) {
            int kk = ks * 16;
            unsigned afr[4][4], bfr[4][2];
#pragma unroll
            for (int mt = 0; mt < 4; mt++) {
                int i0 = wi * 64 + mt * 16;
                const __nv_bfloat16* p = &smA[buf][kk + ((g >> 1) << 3) + r][i0 + ((g & 1) << 3)];
                ldsm4t(afr[mt][0], afr[mt][1], afr[mt][2], afr[mt][3], p);
            }
#pragma unroll
            for (int n2 = 0; n2 < 2; n2++) {
                int j0 = wj * 32 + n2 * 16;
                const __nv_bfloat16* p = &smBsel[buf][kk + ((g & 1) << 3) + r][j0 + ((g >> 1) << 3)];
                unsigned d0, d1, d2, d3;
                ldsm4t(d0, d1, d2, d3, p);
                bfr[n2 * 2][0] = d0; bfr[n2 * 2][1] = d1;
                bfr[n2 * 2 + 1][0] = d2; bfr[n2 * 2 + 1][1] = d3;
            }
#pragma unroll
            for (int mt = 0; mt < 4; mt++)
#pragma unroll
                for (int nt = 0; nt < 4; nt++) mma16816(acc[mt][nt], afr[mt], bfr[nt]);
        }
    }

    // ---- v (solvers set it ~20us; earliest epilogue ~80us; proven spin) ----
    if (tid == 0) { while (ldv_acq(&g_v_ready) == 0u) __nanosleep(20); }
    __syncthreads();
    for (int j = tid; j < N_DIM; j += 256) p_s[j] = __ldcg(&g_v[j]);
    __syncthreads();

    // epilogue: partial = sum Gamma_ij v_i v_j C_ij over this CTA's tile
    float partf = 0.f;
#pragma unroll
    for (int mt = 0; mt < 4; mt++) {
        int ibase = ti + wi * 64 + mt * 16 + (lane >> 2);
#pragma unroll
        for (int nt = 0; nt < 4; nt++) {
            int jbase = tj + wj * 32 + nt * 8 + 2 * (lane & 3);
#pragma unroll
            for (int e = 0; e < 4; e++) {
                int i = ibase + ((e >> 1) << 3);
                int j = jbase + (e & 1);
                partf += acc[mt][nt][e] * Gamma[(size_t)i * N_DIM + j] * p_s[i] * p_s[j];
            }
        }
    }
#pragma unroll
    for (int o = 16; o > 0; o >>= 1) partf += __shfl_xor_sync(0xffffffffu, partf, o);
    if (lane == 0) wsum[wid] = (double)partf;
    __syncthreads();
    if (tid == 0) {
        double sv = 0.0;
        for (int x = 0; x < 8; x++) sv += wsum[x];
        if (ti != tj) sv *= 2.0;   // off-diagonal tiles counted twice (symmetry)
        atomicAdd(&g_second, sv);
        __threadfence();
        unsigned d = atomicAdd(&g_done, 1u);
        is_last = (d == NTOT - 1);
    }
    __syncthreads();

    // ---------------- last CTA finalizes + resets for next replay ----------------
    if (is_last) {
        double term = 0.0;
        for (int j = tid; j < N_DIM; j += 256)
            term += (double)__ldcg(&g_colsum[j]) * (double)p_s[j] * (double)SR[j];
#pragma unroll
        for (int o = 16; o > 0; o >>= 1) term += __shfl_xor_sync(0xffffffffu, term, o);
        if (lane == 0) wsum[wid] = term;
        __syncthreads();
        if (tid == 0) {
            double sf = 0.0;
            for (int x = 0; x < 8; x++) sf += wsum[x];
            double sec = atomicAdd(&g_second, 0.0);   // writers fenced before g_done
            double k = (double)kp[0];
            out[0] = (float)((0.5 * sec - sf) / ((double)B_TOT * k));
        }
        __syncthreads();
        // self-clean device state for the next graph replay
        for (int j = tid; j < N_DIM; j += 256) g_colsum[j] = 0.f;
        if (tid == 0) {
            g_second = 0.0;
            g_done = 0u; g_vcnt = 0u; g_v_ready = 0u;
            g_bar_count = 0u; g_bar_gen = 0u;
            g_cntA = 0u; g_cntB = 0u;
        }
    }
}

// ------------------------------ launch ------------------------------
extern "C" void kernel_launch(void* const* d_in, const int* in_sizes, int n_in,
                              void* d_out, int out_size) {
    const float* lsh = (const float*)d_in[0];
    const float* sig = (const float*)d_in[1];
    const float* SR  = (const float*)d_in[2];
    const float* Gam = (const float*)d_in[3];
    const int*   kp  = (const int*)d_in[4];

    mono_k<<<NTOT, 256>>>(Gam, SR, lsh, sig, kp, (float*)d_out);
}